// round 6
// baseline (speedup 1.0000x reference)
#include <cuda_runtime.h>

#define BB 512
#define DD 512
#define NN 196
#define TT 8            // n-tile width
#define NT 25           // 24 full tiles + 1 remainder (4 cols)
#define TS 516          // transposed smem row stride (even -> float2-aligned)
#define SEG (TT * TS)   // one array buffer = 4128 floats

// scratch (no cudaMalloc allowed)
__device__ float g_mem[BB * DD];
__device__ float g_v1[BB * DD];
__device__ float g_v2[BB * DD];

// ---------------------------------------------------------------------------
// Fused GEMM:  mem = ms @ Wm^T + bm          (f-tiles 0..7)
//              v   = (ctrl*Wattn) @ Wcat     (f-tiles 8..23 -> v1 | v2)
// 32(b) x 64(f) tile, 128 threads, 4x4 per thread, k-tile 16. grid 24x16=384.
// ---------------------------------------------------------------------------
__global__ __launch_bounds__(128) void gemm_kernel(
    const float* __restrict__ ms, const float* __restrict__ Wm,
    const float* __restrict__ bm, const float* __restrict__ ctrl,
    const float* __restrict__ Wattn, const float* __restrict__ Wcat,
    float* __restrict__ memo, float* __restrict__ v1, float* __restrict__ v2)
{
    __shared__ float As[16][36];
    __shared__ float Bs[16][68];
    const int t = threadIdx.x;
    const int tx = t & 15, ty = t >> 4;           // ty 0..7
    const int b0 = blockIdx.y * 32;
    const bool is_mem = (blockIdx.x < 8);
    const int f0 = is_mem ? blockIdx.x * 64 : (blockIdx.x - 8) * 64;
    const int arow = t >> 2, kq = (t & 3) << 2;   // arow 0..31
    float acc[4][4] = {};

    for (int k0 = 0; k0 < DD; k0 += 16) {
        float4 av;
        if (is_mem) {
            av = *(const float4*)(ms + (b0 + arow) * DD + k0 + kq);
        } else {
            float4 c4 = *(const float4*)(ctrl + (b0 + arow) * DD + k0 + kq);
            float4 w4 = *(const float4*)(Wattn + k0 + kq);
            av = make_float4(c4.x * w4.x, c4.y * w4.y, c4.z * w4.z, c4.w * w4.w);
        }
        As[kq + 0][arow] = av.x; As[kq + 1][arow] = av.y;
        As[kq + 2][arow] = av.z; As[kq + 3][arow] = av.w;

        if (is_mem) {  // Wm[f][k] -> transpose to Bs[k][f]
#pragma unroll
            for (int r = 0; r < 2; r++) {
                int idx = t + 128 * r;
                int fr = idx >> 2, kk = (idx & 3) << 2;
                float4 bv = *(const float4*)(Wm + (f0 + fr) * DD + k0 + kk);
                Bs[kk + 0][fr] = bv.x; Bs[kk + 1][fr] = bv.y;
                Bs[kk + 2][fr] = bv.z; Bs[kk + 3][fr] = bv.w;
            }
        } else {       // Wcat[k][f] already k-major
#pragma unroll
            for (int r = 0; r < 2; r++) {
                int idx = t + 128 * r;
                int kk = idx >> 4, fq = (idx & 15) << 2;
                *(float4*)&Bs[kk][fq] =
                    *(const float4*)(Wcat + (size_t)(k0 + kk) * (2 * DD) + f0 + fq);
            }
        }
        __syncthreads();
#pragma unroll
        for (int k = 0; k < 16; k++) {
            float4 a = *(const float4*)&As[k][ty * 4];
            float4 b = *(const float4*)&Bs[k][tx * 4];
            float aa[4] = {a.x, a.y, a.z, a.w};
            float bb[4] = {b.x, b.y, b.z, b.w};
#pragma unroll
            for (int r = 0; r < 4; r++)
#pragma unroll
                for (int c = 0; c < 4; c++) acc[r][c] += aa[r] * bb[c];
        }
        __syncthreads();
    }

#pragma unroll
    for (int r = 0; r < 4; r++) {
        int b = b0 + ty * 4 + r;
#pragma unroll
        for (int c = 0; c < 4; c++) {
            int f = f0 + tx * 4 + c;
            if (is_mem)      memo[b * DD + f] = acc[r][c] + bm[f];
            else if (f < DD) v1[b * DD + f] = acc[r][c];
            else             v2[b * DD + (f - DD)] = acc[r][c];
        }
    }
}

// ---------------------------------------------------------------------------
// Persistent flash attention-read. grid=256, block=512, 2 batches per block,
// 2 CTAs per SM (70.3 KB smem each). Transposed tiles T[n][d] (stride 516):
// conflict-free STS, row reads (logits), column reads (output).
// Thread tid loads/owns d = tid. <=3 syncthreads per tile.
// ---------------------------------------------------------------------------
__global__ __launch_bounds__(512, 2) void attn_kernel(
    const float* __restrict__ kb, const float* __restrict__ kbp,
    const float* __restrict__ memo, const float* __restrict__ v1,
    const float* __restrict__ v2, float* __restrict__ out)
{
    extern __shared__ float smf[];
    float* su1  = smf + 2 * 2 * SEG;   // +16512
    float* su2  = su1 + DD;
    float* slog = su2 + DD;            // [16]  (n 0..7  x  d-half 0..1)
    float* sexp = slog + 16;           // [8]
    float* sred = sexp + 8;            // [0]=scale [1]=tile_sum [2]=Mnew

    const int tid = threadIdx.x;
    const int w = tid >> 5, lane = tid & 31;
    const int b0 = blockIdx.x * 2;
    float4 r0, r1, q0, q1;             // kb row (8 floats), kbp row (8 floats)

    // ---- prefetch step 0 (batch b0, tile 0): row d = tid, cols 0..7 ----
    {
        const float* pk = kb  + (size_t)b0 * DD * NN + tid * NN;
        const float* pp = kbp + (size_t)b0 * DD * NN + tid * NN;
        r0 = *(const float4*)(pk);     r1 = *(const float4*)(pk + 4);
        q0 = *(const float4*)(pp);     q1 = *(const float4*)(pp + 4);
    }

    float M = -1e30f, S = 0.f, o = 0.f;

    for (int s = 0; s < 2 * NT; s++) {
        const int t = s % NT;
        const int b = b0 + s / NT;
        const int valid = (t == NT - 1) ? 4 : TT;
        float* Tkb = smf + (s & 1) * 2 * SEG;
        float* Tkp = Tkb + SEG;

        // ---- STS current tile (transposed; consecutive-lane d -> no conflicts)
        {
            float* c1 = Tkb + tid;
            float* c2 = Tkp + tid;
            c1[0 * TS] = r0.x; c1[1 * TS] = r0.y; c1[2 * TS] = r0.z; c1[3 * TS] = r0.w;
            c2[0 * TS] = q0.x; c2[1 * TS] = q0.y; c2[2 * TS] = q0.z; c2[3 * TS] = q0.w;
            if (valid == TT) {
                c1[4 * TS] = r1.x; c1[5 * TS] = r1.y; c1[6 * TS] = r1.z; c1[7 * TS] = r1.w;
                c2[4 * TS] = q1.x; c2[5 * TS] = q1.y; c2[6 * TS] = q1.z; c2[7 * TS] = q1.w;
            }
        }
        __syncthreads();

        if (t == 0) {  // per-batch u vectors: u1 = v1*mem, u2 = v2
            su1[tid] = v1[b * DD + tid] * memo[b * DD + tid];
            su2[tid] = v2[b * DD + tid];
            __syncthreads();
        }

        // ---- prefetch next step (overlaps compute below) ----
        if (s + 1 < 2 * NT) {
            const int tt = (s + 1) % NT;
            const int bb = b0 + (s + 1) / NT;
            const float* pk = kb  + (size_t)bb * DD * NN + tid * NN + tt * TT;
            const float* pp = kbp + (size_t)bb * DD * NN + tid * NN + tt * TT;
            r0 = *(const float4*)(pk);
            q0 = *(const float4*)(pp);
            if (tt != NT - 1) {
                r1 = *(const float4*)(pk + 4);
                q1 = *(const float4*)(pp + 4);
            }
        }

        // ---- logits: warp w -> n = w&7, d-half = w>>3 (row reads, float2) ----
        {
            const int n = w & 7, h = w >> 3;
            if (n < valid) {
                const float2* rp = (const float2*)(Tkp + n * TS);
                const float2* rb = (const float2*)(Tkb + n * TS);
                const float2* s1 = (const float2*)su1;
                const float2* s2 = (const float2*)su2;
                float p = 0.f;
#pragma unroll
                for (int k = 0; k < 4; k++) {
                    int q = h * 128 + lane + (k << 5);
                    float2 a = rp[q], bv = rb[q];
                    float2 x1 = s1[q], x2 = s2[q];
                    p += x1.x * a.x + x1.y * a.y + x2.x * bv.x + x2.y * bv.y;
                }
#pragma unroll
                for (int off = 16; off; off >>= 1)
                    p += __shfl_xor_sync(0xffffffffu, p, off);
                if (!lane) slog[w] = p;
            }
        }
        __syncthreads();

        // ---- warp 0: online softmax bookkeeping ----
        if (tid < 32) {
            float l = -1e30f;
            if (lane < valid) l = slog[lane] + slog[lane + 8];
            float mx = l;
#pragma unroll
            for (int off = 16; off; off >>= 1)
                mx = fmaxf(mx, __shfl_xor_sync(0xffffffffu, mx, off));
            float Mn = fmaxf(M, mx);
            float e = (lane < valid) ? __expf(l - Mn) : 0.f;
            float ts = e;
#pragma unroll
            for (int off = 16; off; off >>= 1)
                ts += __shfl_xor_sync(0xffffffffu, ts, off);
            if (lane < 8) sexp[lane] = e;          // zeros for invalid lanes
            if (!lane) { sred[0] = __expf(M - Mn); sred[1] = ts; sred[2] = Mn; }
        }
        __syncthreads();

        // ---- output: thread owns d = tid (column reads, no conflicts) ----
        const float scale = sred[0];
        float acc = 0.f;
#pragma unroll
        for (int j = 0; j < TT; j++)               // sexp==0 masks invalid rows
            acc += sexp[j] * Tkb[j * TS + tid];
        o = o * scale + acc;
        S = S * scale + sred[1];
        M = sred[2];
        // no trailing sync: next STS hits the other buffer; re-use of this
        // buffer (at s+2) is fenced by the syncs inside step s+1.

        if (t == NT - 1) {
            out[b * DD + tid] = o / S;
            M = -1e30f; S = 0.f; o = 0.f;
        }
    }
}

// ---------------------------------------------------------------------------
extern "C" void kernel_launch(void* const* d_in, const int* in_sizes, int n_in,
                              void* d_out, int out_size)
{
    const float* memory_state   = (const float*)d_in[0];  // [B, D]
    const float* knowledge_base = (const float*)d_in[1];  // [B, D, N]
    const float* ctrl_state     = (const float*)d_in[2];  // [B, D]
    const float* kb_proj        = (const float*)d_in[3];  // [B, D, N]
    const float* W_mem          = (const float*)d_in[4];  // [D, D]
    const float* b_mem          = (const float*)d_in[5];  // [D]
    const float* W_cat          = (const float*)d_in[6];  // [D, 2D]
    // d_in[7] = b_cat, d_in[9] = b_attn: softmax-invariant, dropped exactly
    const float* W_attn         = (const float*)d_in[8];  // [1, D]
    float* out = (float*)d_out;                           // [B, D]

    float* memo; cudaGetSymbolAddress((void**)&memo, g_mem);
    float* v1;   cudaGetSymbolAddress((void**)&v1,  g_v1);
    float* v2;   cudaGetSymbolAddress((void**)&v2,  g_v2);

    const int smem_bytes = (2 * 2 * SEG + 2 * DD + 32) * 4;  // 70.3 KB
    cudaFuncSetAttribute(attn_kernel, cudaFuncAttributeMaxDynamicSharedMemorySize,
                         smem_bytes);

    gemm_kernel<<<dim3(24, 16), 128>>>(memory_state, W_mem, b_mem,
                                       ctrl_state, W_attn, W_cat, memo, v1, v2);
    attn_kernel<<<BB / 2, 512, smem_bytes>>>(knowledge_base, kb_proj,
                                             memo, v1, v2, out);
}

// round 8
// speedup vs baseline: 1.5368x; 1.5368x over previous
#include <cuda_runtime.h>

#define BB 512
#define DD 512
#define NN 196
#define NP 224   // n padded to 7*32

// scratch (no cudaMalloc allowed)
__device__ float g_mem[BB * DD];
__device__ float g_v1[BB * DD];
__device__ float g_v2[BB * DD];

// ---------------------------------------------------------------------------
// Fused GEMM:  mem = ms @ Wm^T + bm          (f-tiles 0..7)
//              v   = (ctrl*Wattn) @ Wcat     (f-tiles 8..23 -> v1 | v2)
// 32(b) x 64(f) tile, 128 threads, 4x4 per thread, k-tile 16. grid 24x16=384.
// ---------------------------------------------------------------------------
__global__ __launch_bounds__(128) void gemm_kernel(
    const float* __restrict__ ms, const float* __restrict__ Wm,
    const float* __restrict__ bm, const float* __restrict__ ctrl,
    const float* __restrict__ Wattn, const float* __restrict__ Wcat,
    float* __restrict__ memo, float* __restrict__ v1, float* __restrict__ v2)
{
    __shared__ float As[16][36];
    __shared__ float Bs[16][68];
    const int t = threadIdx.x;
    const int tx = t & 15, ty = t >> 4;
    const int b0 = blockIdx.y * 32;
    const bool is_mem = (blockIdx.x < 8);
    const int f0 = is_mem ? blockIdx.x * 64 : (blockIdx.x - 8) * 64;
    const int arow = t >> 2, kq = (t & 3) << 2;
    float acc[4][4] = {};

    for (int k0 = 0; k0 < DD; k0 += 16) {
        float4 av;
        if (is_mem) {
            av = *(const float4*)(ms + (b0 + arow) * DD + k0 + kq);
        } else {
            float4 c4 = *(const float4*)(ctrl + (b0 + arow) * DD + k0 + kq);
            float4 w4 = *(const float4*)(Wattn + k0 + kq);
            av = make_float4(c4.x * w4.x, c4.y * w4.y, c4.z * w4.z, c4.w * w4.w);
        }
        As[kq + 0][arow] = av.x; As[kq + 1][arow] = av.y;
        As[kq + 2][arow] = av.z; As[kq + 3][arow] = av.w;

        if (is_mem) {
#pragma unroll
            for (int r = 0; r < 2; r++) {
                int idx = t + 128 * r;
                int fr = idx >> 2, kk = (idx & 3) << 2;
                float4 bv = *(const float4*)(Wm + (f0 + fr) * DD + k0 + kk);
                Bs[kk + 0][fr] = bv.x; Bs[kk + 1][fr] = bv.y;
                Bs[kk + 2][fr] = bv.z; Bs[kk + 3][fr] = bv.w;
            }
        } else {
#pragma unroll
            for (int r = 0; r < 2; r++) {
                int idx = t + 128 * r;
                int kk = idx >> 4, fq = (idx & 15) << 2;
                *(float4*)&Bs[kk][fq] =
                    *(const float4*)(Wcat + (size_t)(k0 + kk) * (2 * DD) + f0 + fq);
            }
        }
        __syncthreads();
#pragma unroll
        for (int k = 0; k < 16; k++) {
            float4 a = *(const float4*)&As[k][ty * 4];
            float4 b = *(const float4*)&Bs[k][tx * 4];
            float aa[4] = {a.x, a.y, a.z, a.w};
            float bb[4] = {b.x, b.y, b.z, b.w};
#pragma unroll
            for (int r = 0; r < 4; r++)
#pragma unroll
                for (int c = 0; c < 4; c++) acc[r][c] += aa[r] * bb[c];
        }
        __syncthreads();
    }

#pragma unroll
    for (int r = 0; r < 4; r++) {
        int b = b0 + ty * 4 + r;
#pragma unroll
        for (int c = 0; c < 4; c++) {
            int f = f0 + tx * 4 + c;
            if (is_mem)      memo[b * DD + f] = acc[r][c] + bm[f];
            else if (f < DD) v1[b * DD + f] = acc[r][c];
            else             v2[b * DD + (f - DD)] = acc[r][c];
        }
    }
}

// ---------------------------------------------------------------------------
// Two-pass attention read. One CTA per batch, 256 threads (8 warps).
// Phase A: partial logits in registers (coalesced streaming, no syncs).
// Reduce + softmax once per batch. Phase C: weighted sum, re-reads kb.
// Only 4 __syncthreads per batch.
// ---------------------------------------------------------------------------
__global__ __launch_bounds__(256) void attn_kernel(
    const float* __restrict__ kb, const float* __restrict__ kbp,
    const float* __restrict__ memo, const float* __restrict__ v1,
    const float* __restrict__ v2, float* __restrict__ out)
{
    __shared__ float su1[DD];
    __shared__ float su2[DD];
    __shared__ float part[8 * NP];
    __shared__ float sw[NP];

    const int b = blockIdx.x;
    const int tid = threadIdx.x;
    const int w = tid >> 5, lane = tid & 31;
    const float* kbB = kb  + (size_t)b * DD * NN;
    const float* kpB = kbp + (size_t)b * DD * NN;

    // u1 = v1*mem, u2 = v2
    su1[tid]       = v1[b * DD + tid]       * memo[b * DD + tid];
    su1[tid + 256] = v1[b * DD + tid + 256] * memo[b * DD + tid + 256];
    su2[tid]       = v2[b * DD + tid];
    su2[tid + 256] = v2[b * DD + tid + 256];
    __syncthreads();

    // ---- Phase A: partial logits. warp w owns d in [w*64, w*64+64). ----
    {
        float acc[7] = {};
        const int d0 = w * 64;
#pragma unroll 2
        for (int dd = 0; dd < 64; dd += 2) {
            const int d = d0 + dd;
            const float a1 = su1[d],     a2 = su2[d];
            const float c1 = su1[d + 1], c2 = su2[d + 1];
            const float* p0 = kpB + (size_t)d * NN;
            const float* k0 = kbB + (size_t)d * NN;
#pragma unroll
            for (int j = 0; j < 6; j++) {
                const int n = lane + 32 * j;
                acc[j] += a1 * p0[n]      + a2 * k0[n]
                        + c1 * p0[NN + n] + c2 * k0[NN + n];
            }
            if (lane < 4) {
                const int n = 192 + lane;
                acc[6] += a1 * p0[n]      + a2 * k0[n]
                        + c1 * p0[NN + n] + c2 * k0[NN + n];
            }
        }
#pragma unroll
        for (int j = 0; j < 7; j++) part[w * NP + lane + 32 * j] = acc[j];
    }
    __syncthreads();

    // ---- reduce partials across warps ----
    if (tid < NP) {
        float s = 0.f;
#pragma unroll
        for (int w2 = 0; w2 < 8; w2++) s += part[w2 * NP + tid];
        sw[tid] = (tid < NN) ? s : -1e30f;
    }
    __syncthreads();

    // ---- softmax (warp 0): sw[n] = exp(l-m)/S ----
    if (w == 0) {
        float l[7];
#pragma unroll
        for (int j = 0; j < 7; j++) l[j] = sw[lane + 32 * j];
        float m = l[0];
#pragma unroll
        for (int j = 1; j < 7; j++) m = fmaxf(m, l[j]);
#pragma unroll
        for (int off = 16; off; off >>= 1)
            m = fmaxf(m, __shfl_xor_sync(0xffffffffu, m, off));
        float e[7], S = 0.f;
#pragma unroll
        for (int j = 0; j < 7; j++) { e[j] = __expf(l[j] - m); S += e[j]; }
#pragma unroll
        for (int off = 16; off; off >>= 1)
            S += __shfl_xor_sync(0xffffffffu, S, off);
        const float inv = 1.f / S;
#pragma unroll
        for (int j = 0; j < 7; j++) sw[lane + 32 * j] = e[j] * inv;
    }
    __syncthreads();

    // ---- Phase C: out[d] = sum_n sw[n]*kb[d,n]. Same warp/d mapping. ----
    {
        float swr[7];
#pragma unroll
        for (int j = 0; j < 7; j++) swr[j] = sw[lane + 32 * j];
        const int d0 = w * 64;
#pragma unroll 2
        for (int dd = 0; dd < 64; dd += 2) {
            const int d = d0 + dd;
            const float* k0 = kbB + (size_t)d * NN;
            float s0 = 0.f, s1 = 0.f;
#pragma unroll
            for (int j = 0; j < 6; j++) {
                const int n = lane + 32 * j;
                s0 += swr[j] * k0[n];
                s1 += swr[j] * k0[NN + n];
            }
            if (lane < 4) {
                s0 += swr[6] * k0[192 + lane];
                s1 += swr[6] * k0[NN + 192 + lane];
            }
#pragma unroll
            for (int off = 16; off; off >>= 1) {
                s0 += __shfl_xor_sync(0xffffffffu, s0, off);
                s1 += __shfl_xor_sync(0xffffffffu, s1, off);
            }
            if (!lane) *(float2*)(out + b * DD + d) = make_float2(s0, s1);
        }
    }
}

// ---------------------------------------------------------------------------
extern "C" void kernel_launch(void* const* d_in, const int* in_sizes, int n_in,
                              void* d_out, int out_size)
{
    const float* memory_state   = (const float*)d_in[0];  // [B, D]
    const float* knowledge_base = (const float*)d_in[1];  // [B, D, N]
    const float* ctrl_state     = (const float*)d_in[2];  // [B, D]
    const float* kb_proj        = (const float*)d_in[3];  // [B, D, N]
    const float* W_mem          = (const float*)d_in[4];  // [D, D]
    const float* b_mem          = (const float*)d_in[5];  // [D]
    const float* W_cat          = (const float*)d_in[6];  // [D, 2D]
    // d_in[7] = b_cat, d_in[9] = b_attn: softmax-invariant, dropped exactly
    const float* W_attn         = (const float*)d_in[8];  // [1, D]
    float* out = (float*)d_out;                           // [B, D]

    float* memo; cudaGetSymbolAddress((void**)&memo, g_mem);
    float* v1;   cudaGetSymbolAddress((void**)&v1,  g_v1);
    float* v2;   cudaGetSymbolAddress((void**)&v2,  g_v2);

    gemm_kernel<<<dim3(24, 16), 128>>>(memory_state, W_mem, b_mem,
                                       ctrl_state, W_attn, W_cat, memo, v1, v2);
    attn_kernel<<<BB, 256>>>(knowledge_base, kb_proj, memo, v1, v2, out);
}